// round 1
// baseline (speedup 1.0000x reference)
#include <cuda_runtime.h>
#include <cstdint>

// score[e] = dot(h[src[e]], h[dst[e]]), D_FEAT = 128, fp32.
// One warp per edge: lane l handles float4 chunk l of the 128-float row.
// Node table (51.2 MB) fits in GB300's 126 MB L2 -> gathers are L2-resident.

static constexpr int D_FEAT = 128;
static constexpr int VEC_PER_ROW = D_FEAT / 4;  // 32 float4 per row = 1 per lane

__global__ void __launch_bounds__(256)
edge_dot_kernel(const float4* __restrict__ h4,
                const int*    __restrict__ src,
                const int*    __restrict__ dst,
                float*        __restrict__ out,
                int n_edges)
{
    const int gtid = blockIdx.x * blockDim.x + threadIdx.x;
    const int edge = gtid >> 5;
    const int lane = gtid & 31;
    if (edge >= n_edges) return;

    // Warp-uniform index loads (broadcast, single sector each).
    const long long s = src[edge];
    const long long d = dst[edge];

    const float4 a = h4[s * VEC_PER_ROW + lane];
    const float4 b = h4[d * VEC_PER_ROW + lane];

    float sum = a.x * b.x + a.y * b.y + a.z * b.z + a.w * b.w;

    #pragma unroll
    for (int off = 16; off > 0; off >>= 1)
        sum += __shfl_xor_sync(0xFFFFFFFFu, sum, off);

    if (lane == 0) out[edge] = sum;
}

extern "C" void kernel_launch(void* const* d_in, const int* in_sizes, int n_in,
                              void* d_out, int out_size)
{
    const float4* h4  = (const float4*)d_in[0];   // h: [N_NODES, 128] fp32
    const int*    src = (const int*)d_in[1];      // [E] int32
    const int*    dst = (const int*)d_in[2];      // [E] int32
    float*        out = (float*)d_out;            // [E, 1] fp32

    const int n_edges = in_sizes[1];

    const int threads = 256;                       // 8 warps = 8 edges / block
    const int edges_per_block = threads / 32;
    const int blocks = (n_edges + edges_per_block - 1) / edges_per_block;

    edge_dot_kernel<<<blocks, threads>>>(h4, src, dst, out, n_edges);
}

// round 2
// speedup vs baseline: 2.0491x; 2.0491x over previous
#include <cuda_runtime.h>
#include <cstdint>

// score[e] = dot(h[src[e]], h[dst[e]]), D_FEAT = 128, fp32.
// 8 lanes per edge: lane loads 4 float4 per row (MLP=8 across both rows),
// 3-step shfl reduce within the 8-lane group. 4 edges per warp.

static constexpr int VEC_PER_ROW = 32;   // 128 floats = 32 float4
static constexpr int LANES_PER_EDGE = 8;
static constexpr int V_PER_LANE = VEC_PER_ROW / LANES_PER_EDGE;  // 4

__global__ void __launch_bounds__(256)
edge_dot_kernel(const float4* __restrict__ h4,
                const int*    __restrict__ src,
                const int*    __restrict__ dst,
                float*        __restrict__ out,
                int n_edges)
{
    const int gtid = blockIdx.x * blockDim.x + threadIdx.x;
    const int edge = gtid >> 3;          // 8 lanes per edge
    const int sub  = gtid & 7;
    if (edge >= n_edges) return;

    const long long s = src[edge];
    const long long d = dst[edge];

    const float4* __restrict__ arow = h4 + s * VEC_PER_ROW;
    const float4* __restrict__ brow = h4 + d * VEC_PER_ROW;

    // Issue all 8 loads up front for maximum MLP.
    float4 a[V_PER_LANE], b[V_PER_LANE];
    #pragma unroll
    for (int j = 0; j < V_PER_LANE; j++)
        a[j] = arow[sub + j * LANES_PER_EDGE];
    #pragma unroll
    for (int j = 0; j < V_PER_LANE; j++)
        b[j] = brow[sub + j * LANES_PER_EDGE];

    float sum = 0.0f;
    #pragma unroll
    for (int j = 0; j < V_PER_LANE; j++) {
        sum += a[j].x * b[j].x;
        sum += a[j].y * b[j].y;
        sum += a[j].z * b[j].z;
        sum += a[j].w * b[j].w;
    }

    // Reduce across the 8-lane group.
    #pragma unroll
    for (int off = 4; off > 0; off >>= 1)
        sum += __shfl_xor_sync(0xFFFFFFFFu, sum, off);

    if (sub == 0) out[edge] = sum;
}

extern "C" void kernel_launch(void* const* d_in, const int* in_sizes, int n_in,
                              void* d_out, int out_size)
{
    const float4* h4  = (const float4*)d_in[0];   // h: [N_NODES, 128] fp32
    const int*    src = (const int*)d_in[1];      // [E] int32
    const int*    dst = (const int*)d_in[2];      // [E] int32
    float*        out = (float*)d_out;            // [E] fp32

    const int n_edges = in_sizes[1];

    const int threads = 256;                               // 32 edges / block
    const int edges_per_block = threads / LANES_PER_EDGE;
    const int blocks = (n_edges + edges_per_block - 1) / edges_per_block;

    edge_dot_kernel<<<blocks, threads>>>(h4, src, dst, out, n_edges);
}

// round 3
// speedup vs baseline: 2.3371x; 1.1405x over previous
#include <cuda_runtime.h>
#include <cstdint>

// score[e] = dot(h[src[e]], h[dst[e]]), D_FEAT = 128, fp32.
// 8 lanes per edge-pair group: each group handles 2 consecutive edges.
// Each thread issues 16 independent LDG.128 up front (MLP=16), then two
// dot products and two overlapped 3-step shfl reductions.

static constexpr int VEC_PER_ROW = 32;   // 128 floats = 32 float4
static constexpr int LANES_PER_EDGE = 8;
static constexpr int V_PER_LANE = VEC_PER_ROW / LANES_PER_EDGE;  // 4

__global__ void __launch_bounds__(256)
edge_dot_kernel(const float4* __restrict__ h4,
                const int*    __restrict__ src,
                const int*    __restrict__ dst,
                float*        __restrict__ out,
                int n_edges)
{
    const int gtid  = blockIdx.x * blockDim.x + threadIdx.x;
    const int group = gtid >> 3;         // 8 lanes per group, 2 edges per group
    const int sub   = gtid & 7;

    const int e0 = group * 2;
    const int e1 = e0 + 1;
    if (e0 >= n_edges) return;
    const bool has_e1 = (e1 < n_edges);

    const long long s0 = src[e0];
    const long long d0 = dst[e0];
    const long long s1 = has_e1 ? (long long)src[e1] : s0;
    const long long d1 = has_e1 ? (long long)dst[e1] : d0;

    const float4* __restrict__ a0r = h4 + s0 * VEC_PER_ROW;
    const float4* __restrict__ b0r = h4 + d0 * VEC_PER_ROW;
    const float4* __restrict__ a1r = h4 + s1 * VEC_PER_ROW;
    const float4* __restrict__ b1r = h4 + d1 * VEC_PER_ROW;

    // Issue all 16 loads up front for maximum MLP.
    float4 a0[V_PER_LANE], b0[V_PER_LANE], a1[V_PER_LANE], b1[V_PER_LANE];
    #pragma unroll
    for (int j = 0; j < V_PER_LANE; j++) a0[j] = a0r[sub + j * LANES_PER_EDGE];
    #pragma unroll
    for (int j = 0; j < V_PER_LANE; j++) b0[j] = b0r[sub + j * LANES_PER_EDGE];
    #pragma unroll
    for (int j = 0; j < V_PER_LANE; j++) a1[j] = a1r[sub + j * LANES_PER_EDGE];
    #pragma unroll
    for (int j = 0; j < V_PER_LANE; j++) b1[j] = b1r[sub + j * LANES_PER_EDGE];

    float sum0 = 0.0f, sum1 = 0.0f;
    #pragma unroll
    for (int j = 0; j < V_PER_LANE; j++) {
        sum0 += a0[j].x * b0[j].x;
        sum0 += a0[j].y * b0[j].y;
        sum0 += a0[j].z * b0[j].z;
        sum0 += a0[j].w * b0[j].w;
        sum1 += a1[j].x * b1[j].x;
        sum1 += a1[j].y * b1[j].y;
        sum1 += a1[j].z * b1[j].z;
        sum1 += a1[j].w * b1[j].w;
    }

    // Two overlapped butterfly reductions across the 8-lane group.
    #pragma unroll
    for (int off = 4; off > 0; off >>= 1) {
        sum0 += __shfl_xor_sync(0xFFFFFFFFu, sum0, off);
        sum1 += __shfl_xor_sync(0xFFFFFFFFu, sum1, off);
    }

    if (sub == 0) out[e0] = sum0;
    if (sub == 1 && has_e1) out[e1] = sum1;
}

extern "C" void kernel_launch(void* const* d_in, const int* in_sizes, int n_in,
                              void* d_out, int out_size)
{
    const float4* h4  = (const float4*)d_in[0];   // h: [N_NODES, 128] fp32
    const int*    src = (const int*)d_in[1];      // [E] int32
    const int*    dst = (const int*)d_in[2];      // [E] int32
    float*        out = (float*)d_out;            // [E] fp32

    const int n_edges = in_sizes[1];

    const int threads = 256;
    const int edges_per_block = (threads / LANES_PER_EDGE) * 2;  // 64
    const int blocks = (n_edges + edges_per_block - 1) / edges_per_block;

    edge_dot_kernel<<<blocks, threads>>>(h4, src, dst, out, n_edges);
}

// round 4
// speedup vs baseline: 2.3487x; 1.0050x over previous
#include <cuda_runtime.h>
#include <cstdint>

// score[e] = dot(h[src[e]], h[dst[e]]), D_FEAT = 128, fp32.
// 8 lanes per group, 2 edges per group. Each lane covers its 128B share of a
// 512B node row with 2x LDG.256 (ld.global.v8.b32, sm_100+). 8 load
// instructions / 2KB in flight per thread. int2 index loads, 32-bit byte math.

static constexpr int LANES_PER_EDGE = 8;
static constexpr int ROW_BYTES = 128 * 4;      // 512
static constexpr int CHUNK_BYTES = 32;         // per LDG.256 per lane

struct F8 { float v[8]; };

__device__ __forceinline__ F8 ldg256(const void* p) {
    unsigned r0, r1, r2, r3, r4, r5, r6, r7;
    asm volatile("ld.global.v8.b32 {%0,%1,%2,%3,%4,%5,%6,%7}, [%8];"
                 : "=r"(r0), "=r"(r1), "=r"(r2), "=r"(r3),
                   "=r"(r4), "=r"(r5), "=r"(r6), "=r"(r7)
                 : "l"(p));
    F8 f;
    f.v[0] = __uint_as_float(r0); f.v[1] = __uint_as_float(r1);
    f.v[2] = __uint_as_float(r2); f.v[3] = __uint_as_float(r3);
    f.v[4] = __uint_as_float(r4); f.v[5] = __uint_as_float(r5);
    f.v[6] = __uint_as_float(r6); f.v[7] = __uint_as_float(r7);
    return f;
}

__global__ void __launch_bounds__(256)
edge_dot_kernel(const char* __restrict__ hbase,
                const int2* __restrict__ src2,
                const int2* __restrict__ dst2,
                float*      __restrict__ out,
                int n_edges)
{
    const int gtid  = blockIdx.x * blockDim.x + threadIdx.x;
    const int group = gtid >> 3;            // 8 lanes per group, 2 edges each
    const int sub   = gtid & 7;

    const int e0 = group * 2;
    if (e0 >= n_edges) return;
    const bool has_e1 = (e0 + 1 < n_edges);

    // Paired index loads (e0 is even -> int2-aligned).
    const int2 s01 = src2[group];
    const int2 d01 = dst2[group];

    // 32-bit byte offsets (max 100k * 512 = 51.2MB < 2^31).
    const unsigned c0 = (unsigned)sub * CHUNK_BYTES;           // chunk sub
    const unsigned c1 = c0 + LANES_PER_EDGE * CHUNK_BYTES;     // chunk sub+8

    const char* a0p = hbase + (unsigned)s01.x * ROW_BYTES;
    const char* b0p = hbase + (unsigned)d01.x * ROW_BYTES;
    const char* a1p = hbase + (unsigned)(has_e1 ? s01.y : s01.x) * ROW_BYTES;
    const char* b1p = hbase + (unsigned)(has_e1 ? d01.y : d01.x) * ROW_BYTES;

    // 8 independent 256-bit loads, all issued up front.
    F8 a00 = ldg256(a0p + c0);
    F8 a01 = ldg256(a0p + c1);
    F8 b00 = ldg256(b0p + c0);
    F8 b01 = ldg256(b0p + c1);
    F8 a10 = ldg256(a1p + c0);
    F8 a11 = ldg256(a1p + c1);
    F8 b10 = ldg256(b1p + c0);
    F8 b11 = ldg256(b1p + c1);

    float sum0 = 0.0f, sum1 = 0.0f;
    #pragma unroll
    for (int k = 0; k < 8; k++) {
        sum0 += a00.v[k] * b00.v[k];
        sum0 += a01.v[k] * b01.v[k];
        sum1 += a10.v[k] * b10.v[k];
        sum1 += a11.v[k] * b11.v[k];
    }

    // Butterfly reduce across the 8-lane group (both edges overlapped).
    #pragma unroll
    for (int off = 4; off > 0; off >>= 1) {
        sum0 += __shfl_xor_sync(0xFFFFFFFFu, sum0, off);
        sum1 += __shfl_xor_sync(0xFFFFFFFFu, sum1, off);
    }

    if (sub == 0) out[e0] = sum0;
    if (sub == 1 && has_e1) out[e0 + 1] = sum1;
}

extern "C" void kernel_launch(void* const* d_in, const int* in_sizes, int n_in,
                              void* d_out, int out_size)
{
    const char* hbase = (const char*)d_in[0];   // h: [N_NODES, 128] fp32
    const int2* src2  = (const int2*)d_in[1];   // [E] int32, read as pairs
    const int2* dst2  = (const int2*)d_in[2];
    float*      out   = (float*)d_out;          // [E] fp32

    const int n_edges = in_sizes[1];

    const int threads = 256;
    const int edges_per_block = (threads / LANES_PER_EDGE) * 2;  // 64
    const int blocks = (n_edges + edges_per_block - 1) / edges_per_block;

    edge_dot_kernel<<<blocks, threads>>>(hbase, src2, dst2, out, n_edges);
}

// round 6
// speedup vs baseline: 3.5768x; 1.5228x over previous
#include <cuda_runtime.h>
#include <cuda_fp16.h>
#include <cstdint>
#include <cstring>

// score[e] = dot(h[src[e]], h[dst[e]]), D = 128.
// Pass 1: convert fp32 node table -> fp16 scratch (halves L2 gather traffic).
// Pass 2: gather fp16 rows (256B each), dot in fp32, 8 lanes/edge, 4 edges/group.

static constexpr int MAX_NODES = 100000;
static constexpr int D_FEAT = 128;
static constexpr int ROW_BYTES = D_FEAT * 2;        // 256B per fp16 row
static constexpr int LANES_PER_EDGE = 8;
static constexpr int CHUNK_BYTES = 32;              // 16 halves per lane

__device__ __align__(256) static __half g_h16[MAX_NODES * D_FEAT];  // 25.6 MB scratch

__device__ __forceinline__ unsigned h2_as_u32(__half2 h) {
    unsigned u;
    memcpy(&u, &h, 4);
    return u;
}
__device__ __forceinline__ __half2 u32_as_h2(unsigned u) {
    __half2 h;
    memcpy(&h, &u, 4);
    return h;
}

// ---------------- Pass 1: fp32 -> fp16 conversion --------------------------
__global__ void __launch_bounds__(256)
convert_kernel(const float4* __restrict__ h4, int n_pairs)  // n_pairs = total_floats/8
{
    int i = blockIdx.x * blockDim.x + threadIdx.x;
    if (i >= n_pairs) return;
    float4 x = h4[2 * i];
    float4 y = h4[2 * i + 1];
    uint4 packed;
    packed.x = h2_as_u32(__floats2half2_rn(x.x, x.y));
    packed.y = h2_as_u32(__floats2half2_rn(x.z, x.w));
    packed.z = h2_as_u32(__floats2half2_rn(y.x, y.y));
    packed.w = h2_as_u32(__floats2half2_rn(y.z, y.w));
    reinterpret_cast<uint4*>(g_h16)[i] = packed;
}

// ---------------- Pass 2: edge dot on fp16 table ---------------------------
struct U8 { unsigned v[8]; };

__device__ __forceinline__ U8 ldg256(const void* p) {
    U8 u;
    asm volatile("ld.global.v8.b32 {%0,%1,%2,%3,%4,%5,%6,%7}, [%8];"
                 : "=r"(u.v[0]), "=r"(u.v[1]), "=r"(u.v[2]), "=r"(u.v[3]),
                   "=r"(u.v[4]), "=r"(u.v[5]), "=r"(u.v[6]), "=r"(u.v[7])
                 : "l"(p));
    return u;
}

__device__ __forceinline__ float dot16(const U8& a, const U8& b) {
    float s = 0.0f;
    #pragma unroll
    for (int j = 0; j < 8; j++) {
        float2 fa = __half22float2(u32_as_h2(a.v[j]));
        float2 fb = __half22float2(u32_as_h2(b.v[j]));
        s += fa.x * fb.x;
        s += fa.y * fb.y;
    }
    return s;
}

__global__ void __launch_bounds__(256)
edge_dot_kernel(const int* __restrict__ src,
                const int* __restrict__ dst,
                float*     __restrict__ out,
                int n_edges)
{
    const int gtid  = blockIdx.x * blockDim.x + threadIdx.x;
    const int group = gtid >> 3;            // 8 lanes per group, 4 edges each
    const int sub   = gtid & 7;

    const int e0 = group * 4;
    if (e0 >= n_edges) return;

    // Index loads: int4 when the full quad is in range (e0 is 4-aligned).
    int4 s, d;
    if (e0 + 3 < n_edges) {
        s = reinterpret_cast<const int4*>(src)[group];
        d = reinterpret_cast<const int4*>(dst)[group];
    } else {
        int last = n_edges - 1;
        s.x = src[e0];
        s.y = src[min(e0 + 1, last)];
        s.z = src[min(e0 + 2, last)];
        s.w = src[min(e0 + 3, last)];
        d.x = dst[e0];
        d.y = dst[min(e0 + 1, last)];
        d.z = dst[min(e0 + 2, last)];
        d.w = dst[min(e0 + 3, last)];
    }

    const char* base = reinterpret_cast<const char*>(g_h16);
    const unsigned off = (unsigned)sub * CHUNK_BYTES;

    // 8 independent 256-bit loads, all issued up front (2KB in flight/thread).
    U8 a0 = ldg256(base + (unsigned)s.x * ROW_BYTES + off);
    U8 b0 = ldg256(base + (unsigned)d.x * ROW_BYTES + off);
    U8 a1 = ldg256(base + (unsigned)s.y * ROW_BYTES + off);
    U8 b1 = ldg256(base + (unsigned)d.y * ROW_BYTES + off);
    U8 a2 = ldg256(base + (unsigned)s.z * ROW_BYTES + off);
    U8 b2 = ldg256(base + (unsigned)d.z * ROW_BYTES + off);
    U8 a3 = ldg256(base + (unsigned)s.w * ROW_BYTES + off);
    U8 b3 = ldg256(base + (unsigned)d.w * ROW_BYTES + off);

    float sum0 = dot16(a0, b0);
    float sum1 = dot16(a1, b1);
    float sum2 = dot16(a2, b2);
    float sum3 = dot16(a3, b3);

    // Four overlapped butterfly reductions across the 8-lane group.
    #pragma unroll
    for (int offr = 4; offr > 0; offr >>= 1) {
        sum0 += __shfl_xor_sync(0xFFFFFFFFu, sum0, offr);
        sum1 += __shfl_xor_sync(0xFFFFFFFFu, sum1, offr);
        sum2 += __shfl_xor_sync(0xFFFFFFFFu, sum2, offr);
        sum3 += __shfl_xor_sync(0xFFFFFFFFu, sum3, offr);
    }

    if (sub == 0)                        out[e0]     = sum0;
    if (sub == 1 && e0 + 1 < n_edges)    out[e0 + 1] = sum1;
    if (sub == 2 && e0 + 2 < n_edges)    out[e0 + 2] = sum2;
    if (sub == 3 && e0 + 3 < n_edges)    out[e0 + 3] = sum3;
}

extern "C" void kernel_launch(void* const* d_in, const int* in_sizes, int n_in,
                              void* d_out, int out_size)
{
    const float4* h4  = (const float4*)d_in[0];   // h: [N_NODES, 128] fp32
    const int*    src = (const int*)d_in[1];      // [E] int32
    const int*    dst = (const int*)d_in[2];      // [E] int32
    float*        out = (float*)d_out;            // [E] fp32

    const int n_feat_elems = in_sizes[0];          // N_NODES * 128
    const int n_edges      = in_sizes[1];

    // Pass 1: convert table to fp16 (each thread: 8 floats).
    const int n_pairs = n_feat_elems / 8;
    convert_kernel<<<(n_pairs + 255) / 256, 256>>>(h4, n_pairs);

    // Pass 2: edge dots.
    const int threads = 256;
    const int edges_per_block = (threads / LANES_PER_EDGE) * 4;  // 128
    const int blocks = (n_edges + edges_per_block - 1) / edges_per_block;
    edge_dot_kernel<<<blocks, threads>>>(src, dst, out, n_edges);
}